// round 2
// baseline (speedup 1.0000x reference)
#include <cuda_runtime.h>
#include <cuda_bf16.h>
#include <float.h>
#include <math.h>

// ---------------- problem constants ----------------
#define BB   16
#define EE   400
#define RR   624
#define NN   1024          // E + R
#define HSZ  512
#define HEADS 4
#define DK   128
#define DFF  2048
#define PROP 2
#define RTOKS 40

// ---------------- scratch (device globals; no allocs allowed) ----------------
__device__ float g_x[(long)BB*NN*HSZ];
__device__ float g_q[(long)BB*NN*HSZ];
__device__ float g_k[(long)BB*NN*HSZ];
__device__ float g_v[(long)BB*NN*HSZ];
__device__ float g_o[(long)BB*NN*HSZ];
__device__ float g_t[(long)BB*NN*HSZ];
__device__ float g_h[(long)BB*NN*DFF];
__device__ float g_s[(long)BB*HEADS*NN*NN];

// ---------------- gather: x = concat(ents, renc[rels]) ----------------
__global__ void __launch_bounds__(256) gather_kernel(
    const float* __restrict__ ents, const int* __restrict__ rels,
    const float* __restrict__ renc)
{
    long i = (long)blockIdx.x * 256 + threadIdx.x;          // float4 index
    const long TOT = (long)BB * NN * (HSZ / 4);
    if (i >= TOT) return;
    int c  = (int)(i & (HSZ/4 - 1));                        // 0..127
    long bn = i >> 7;
    int n  = (int)(bn & (NN - 1));
    int b  = (int)(bn >> 10);
    float4 v;
    if (n < EE) {
        v = ((const float4*)ents)[((long)b*EE + n)*(HSZ/4) + c];
    } else {
        int r = rels[b*RR + (n - EE)];
        v = ((const float4*)renc)[(long)r*(HSZ/4) + c];
    }
    ((float4*)g_x)[i] = v;
}

// ---------------- generic 128x128x16 tiled GEMM ----------------
// C[z][m][n] = alpha * sum_k A[z][m][k] * B'[z][k][n]  (+bias)(prelu)(+res)
// TRB=false: B stored [k][n] (ldb over k rows). TRB=true: B stored [n][k].
// Per-z operand offsets: zb*s?b + zh*s?h with zb=z/H, zh=z%H. res shares C strides.
template<bool TRB>
__global__ void __launch_bounds__(256) gemm_tile(
    const float* __restrict__ A, const float* __restrict__ B, float* __restrict__ C,
    int M, int N, int K, int lda, int ldb, int ldc,
    long sAb, long sAh, long sBb, long sBh, long sCb, long sCh,
    int H, float alpha,
    const float* __restrict__ bias,
    const float* __restrict__ prelu,
    const float* __restrict__ res)
{
    int zb = blockIdx.z / H;
    int zh = blockIdx.z - zb * H;
    const float* Ab = A + zb * sAb + zh * sAh;
    const float* Bb = B + zb * sBb + zh * sBh;
    float*       Cb = C + zb * sCb + zh * sCh;
    const float* Rb = res ? (res + zb * sCb + zh * sCh) : nullptr;

    int bm = blockIdx.y << 7;
    int bn = blockIdx.x << 7;

    __shared__ float As[16][128];
    __shared__ float Bs[16][128];

    int tid = threadIdx.x;
    int tx = tid & 15, ty = tid >> 4;

    float acc[8][8];
    #pragma unroll
    for (int i = 0; i < 8; i++)
        #pragma unroll
        for (int j = 0; j < 8; j++) acc[i][j] = 0.f;

    int am = tid >> 2;            // 0..63
    int ac = (tid & 3) << 2;      // 0,4,8,12

    for (int k0 = 0; k0 < K; k0 += 16) {
        // load A tile (transpose into As[k][m])
        #pragma unroll
        for (int half = 0; half < 2; half++) {
            int m = am + half * 64;
            float4 v = *(const float4*)(Ab + (long)(bm + m) * lda + k0 + ac);
            As[ac+0][m] = v.x; As[ac+1][m] = v.y; As[ac+2][m] = v.z; As[ac+3][m] = v.w;
        }
        if (TRB) {
            #pragma unroll
            for (int half = 0; half < 2; half++) {
                int n = am + half * 64;
                float4 v = *(const float4*)(Bb + (long)(bn + n) * ldb + k0 + ac);
                Bs[ac+0][n] = v.x; Bs[ac+1][n] = v.y; Bs[ac+2][n] = v.z; Bs[ac+3][n] = v.w;
            }
        } else {
            int kk = tid >> 5;            // 0..7
            int nc = (tid & 31) << 2;     // 0..124
            #pragma unroll
            for (int half = 0; half < 2; half++) {
                int k = kk + half * 8;
                float4 v = *(const float4*)(Bb + (long)(k0 + k) * ldb + bn + nc);
                *(float4*)&Bs[k][nc] = v;
            }
        }
        __syncthreads();

        #pragma unroll
        for (int kk = 0; kk < 16; kk++) {
            float a[8], bq[8];
            float4 t0 = *(const float4*)&As[kk][ty*4];
            float4 t1 = *(const float4*)&As[kk][ty*4 + 64];
            a[0]=t0.x; a[1]=t0.y; a[2]=t0.z; a[3]=t0.w;
            a[4]=t1.x; a[5]=t1.y; a[6]=t1.z; a[7]=t1.w;
            float4 u0 = *(const float4*)&Bs[kk][tx*4];
            float4 u1 = *(const float4*)&Bs[kk][tx*4 + 64];
            bq[0]=u0.x; bq[1]=u0.y; bq[2]=u0.z; bq[3]=u0.w;
            bq[4]=u1.x; bq[5]=u1.y; bq[6]=u1.z; bq[7]=u1.w;
            #pragma unroll
            for (int i = 0; i < 8; i++)
                #pragma unroll
                for (int j = 0; j < 8; j++)
                    acc[i][j] += a[i] * bq[j];
        }
        __syncthreads();
    }

    // epilogue
    #pragma unroll
    for (int i = 0; i < 8; i++) {
        int row = bm + ty*4 + (i < 4 ? i : 60 + i);
        #pragma unroll
        for (int j = 0; j < 8; j++) {
            int col = bn + tx*4 + (j < 4 ? j : 60 + j);
            float v = acc[i][j] * alpha;
            if (bias)  v += bias[col];
            if (prelu) v = v > 0.f ? v : prelu[col] * v;
            if (Rb)    v += Rb[(long)row * ldc + col];
            Cb[(long)row * ldc + col] = v;
        }
    }
}

// ---------------- masked softmax over S rows ----------------
__global__ void __launch_bounds__(256) softmax_mask_kernel(
    float* __restrict__ S, const int* __restrict__ adj)
{
    int n = blockIdx.x, h = blockIdx.y, b = blockIdx.z;
    float* row = S + ((long)(b*HEADS + h) * NN + n) * NN;
    const int* arow = adj + ((long)b * NN + n) * NN;
    int tid = threadIdx.x;

    float4 v = ((const float4*)row)[tid];
    int4  a = ((const int4*)arow)[tid];
    v.x = a.x ? v.x : -FLT_MAX;
    v.y = a.y ? v.y : -FLT_MAX;
    v.z = a.z ? v.z : -FLT_MAX;
    v.w = a.w ? v.w : -FLT_MAX;

    __shared__ float red[16];
    int lane = tid & 31, wid = tid >> 5;

    float mx = fmaxf(fmaxf(v.x, v.y), fmaxf(v.z, v.w));
    #pragma unroll
    for (int o = 16; o > 0; o >>= 1) mx = fmaxf(mx, __shfl_xor_sync(0xffffffffu, mx, o));
    if (lane == 0) red[wid] = mx;
    __syncthreads();
    mx = red[0];
    #pragma unroll
    for (int w = 1; w < 8; w++) mx = fmaxf(mx, red[w]);

    float e0 = __expf(v.x - mx), e1 = __expf(v.y - mx);
    float e2 = __expf(v.z - mx), e3 = __expf(v.w - mx);
    float s = e0 + e1 + e2 + e3;
    #pragma unroll
    for (int o = 16; o > 0; o >>= 1) s += __shfl_xor_sync(0xffffffffu, s, o);
    if (lane == 0) red[8 + wid] = s;
    __syncthreads();
    s = red[8];
    #pragma unroll
    for (int w = 1; w < 8; w++) s += red[8 + w];

    float inv = 1.f / s;
    float4 o4 = make_float4(e0*inv, e1*inv, e2*inv, e3*inv);
    ((float4*)row)[tid] = o4;
}

// ---------------- layer norm over rows of 512 ----------------
__global__ void __launch_bounds__(128) layernorm_kernel(
    const float* __restrict__ in, float* __restrict__ out,
    const float* __restrict__ gamma, const float* __restrict__ beta)
{
    long row = blockIdx.x;
    int tid = threadIdx.x, lane = tid & 31, wid = tid >> 5;
    float4 v = ((const float4*)(in + row * HSZ))[tid];

    __shared__ float red[8];
    float s = v.x + v.y + v.z + v.w;
    #pragma unroll
    for (int o = 16; o > 0; o >>= 1) s += __shfl_xor_sync(0xffffffffu, s, o);
    if (lane == 0) red[wid] = s;
    __syncthreads();
    float mu = (red[0] + red[1] + red[2] + red[3]) * (1.f / HSZ);

    float dx = v.x - mu, dy = v.y - mu, dz = v.z - mu, dw = v.w - mu;
    float q = dx*dx + dy*dy + dz*dz + dw*dw;
    #pragma unroll
    for (int o = 16; o > 0; o >>= 1) q += __shfl_xor_sync(0xffffffffu, q, o);
    if (lane == 0) red[4 + wid] = q;
    __syncthreads();
    float var = (red[4] + red[5] + red[6] + red[7]) * (1.f / HSZ);
    float rstd = rsqrtf(var + 1e-5f);

    float4 g = ((const float4*)gamma)[tid];
    float4 bb = ((const float4*)beta)[tid];
    float4 o4;
    o4.x = dx * rstd * g.x + bb.x;
    o4.y = dy * rstd * g.y + bb.y;
    o4.z = dz * rstd * g.z + bb.z;
    o4.w = dw * rstd * g.w + bb.w;
    ((float4*)(out + row * HSZ))[tid] = o4;
}

// ---------------- output assembly: [glob | nodes | mask] ----------------
__global__ void __launch_bounds__(256) write_out_kernel(float* __restrict__ out, long out_size)
{
    long i = (long)blockIdx.x * 256 + threadIdx.x;
    if (i >= out_size) return;
    const long G  = (long)BB * HSZ;                 // 8192
    const long ND = (long)BB * NN * HSZ;            // 8388608
    if (i < G) {
        long b = i >> 9;                            // /512
        long c = i & 511;
        out[i] = g_x[(b * NN + EE) * HSZ + c];
    } else if (i < G + ND) {
        out[i] = g_x[i - G];
    } else {
        out[i] = 1.0f;                              // node_mask = True
    }
}

// ---------------- orchestration ----------------
extern "C" void kernel_launch(void* const* d_in, const int* in_sizes, int n_in,
                              void* d_out, int out_size)
{
    const float* ents = (const float*)d_in[0];
    const int*   rels = (const int*)  d_in[1];
    const int*   adj  = (const int*)  d_in[2];
    const float* renc = (const float*)d_in[3];
    const float* Wq   = (const float*)d_in[4];
    const float* Wk   = (const float*)d_in[5];
    const float* Wv   = (const float*)d_in[6];
    const float* l1w  = (const float*)d_in[7];
    const float* l1b  = (const float*)d_in[8];
    const float* l2w  = (const float*)d_in[9];
    const float* l2b  = (const float*)d_in[10];
    const float* ln1s = (const float*)d_in[11];
    const float* ln1b = (const float*)d_in[12];
    const float* ln2s = (const float*)d_in[13];
    const float* ln2b = (const float*)d_in[14];
    const float* pa   = (const float*)d_in[15];

    float *gx, *gq, *gk, *gv, *go, *gt, *gh, *gs;
    cudaGetSymbolAddress((void**)&gx, g_x);
    cudaGetSymbolAddress((void**)&gq, g_q);
    cudaGetSymbolAddress((void**)&gk, g_k);
    cudaGetSymbolAddress((void**)&gv, g_v);
    cudaGetSymbolAddress((void**)&go, g_o);
    cudaGetSymbolAddress((void**)&gt, g_t);
    cudaGetSymbolAddress((void**)&gh, g_h);
    cudaGetSymbolAddress((void**)&gs, g_s);

    const long M = (long)BB * NN;                   // 16384
    const float inv_sqrt_hsz = 0.04419417382415922f; // 1/sqrt(512)

    // gather x
    {
        long tot = M * (HSZ/4);
        gather_kernel<<<(unsigned)((tot + 255) / 256), 256>>>(ents, rels, renc);
    }

    for (int j = 0; j < PROP; j++) {
        const float* wq = Wq + (long)j * HSZ * HSZ;
        const float* wk = Wk + (long)j * HSZ * HSZ;
        const float* wv = Wv + (long)j * HSZ * HSZ;

        // Q,K,V = x @ W*
        gemm_tile<false><<<dim3(HSZ/128, (unsigned)(M/128), 1), 256>>>(
            gx, wq, gq, (int)M, HSZ, HSZ, HSZ, HSZ, HSZ,
            0,0,0,0,0,0, 1, 1.f, nullptr, nullptr, nullptr);
        gemm_tile<false><<<dim3(HSZ/128, (unsigned)(M/128), 1), 256>>>(
            gx, wk, gk, (int)M, HSZ, HSZ, HSZ, HSZ, HSZ,
            0,0,0,0,0,0, 1, 1.f, nullptr, nullptr, nullptr);
        gemm_tile<false><<<dim3(HSZ/128, (unsigned)(M/128), 1), 256>>>(
            gx, wv, gv, (int)M, HSZ, HSZ, HSZ, HSZ, HSZ,
            0,0,0,0,0,0, 1, 1.f, nullptr, nullptr, nullptr);

        // S = (Q @ K^T) / sqrt(HSZ), batched over (b,h)
        gemm_tile<true><<<dim3(NN/128, NN/128, BB*HEADS), 256>>>(
            gq, gk, gs, NN, NN, DK, HSZ, HSZ, NN,
            (long)NN*HSZ, DK, (long)NN*HSZ, DK,
            (long)HEADS*NN*NN, (long)NN*NN,
            HEADS, inv_sqrt_hsz, nullptr, nullptr, nullptr);

        // masked softmax in-place
        softmax_mask_kernel<<<dim3(NN, HEADS, BB), 256>>>(gs, adj);

        // out = S @ V + x   (residual fused)
        gemm_tile<false><<<dim3(DK/128, NN/128, BB*HEADS), 256>>>(
            gs, gv, go, NN, DK, NN, NN, HSZ, HSZ,
            (long)HEADS*NN*NN, (long)NN*NN, (long)NN*HSZ, DK,
            (long)NN*HSZ, DK,
            HEADS, 1.f, nullptr, nullptr, gx);

        // t = LN1(out)
        layernorm_kernel<<<(unsigned)M, 128>>>(go, gt, ln1s + j*HSZ, ln1b + j*HSZ);

        // h = prelu(t @ l1_w + l1_b)
        gemm_tile<false><<<dim3(DFF/128, (unsigned)(M/128), 1), 256>>>(
            gt, l1w + (long)j*HSZ*DFF, gh, (int)M, DFF, HSZ, HSZ, DFF, DFF,
            0,0,0,0,0,0, 1, 1.f, l1b + (long)j*DFF, pa + (long)j*DFF, nullptr);

        // o = h @ l2_w + l2_b + t
        gemm_tile<false><<<dim3(HSZ/128, (unsigned)(M/128), 1), 256>>>(
            gh, l2w + (long)j*DFF*HSZ, go, (int)M, HSZ, DFF, DFF, HSZ, HSZ,
            0,0,0,0,0,0, 1, 1.f, l2b + (long)j*HSZ, nullptr, gt);

        // x = LN2(o)
        layernorm_kernel<<<(unsigned)M, 128>>>(go, gx, ln2s + j*HSZ, ln2b + j*HSZ);
    }

    // assemble output: glob (16*512) | nodes (16*1024*512) | mask (16*1024)
    {
        long os = (long)out_size;
        write_out_kernel<<<(unsigned)((os + 255) / 256), 256>>>((float*)d_out, os);
    }
}

// round 6
// speedup vs baseline: 2.7129x; 2.7129x over previous
#include <cuda_runtime.h>
#include <cuda_bf16.h>
#include <float.h>
#include <math.h>

// ---------------- problem constants ----------------
#define BB   16
#define EE   400
#define RR   624
#define NN   1024          // E + R
#define HSZ  512
#define HEADS 4
#define DK   128
#define DFF  2048
#define PROP 2
#define RTOKS 40

// ---------------- scratch (device globals; no allocs allowed) ----------------
__device__ float g_x[(long)BB*NN*HSZ];
__device__ float g_q[(long)BB*NN*HSZ];
__device__ float g_k[(long)BB*NN*HSZ];
__device__ float g_v[(long)BB*NN*HSZ];
__device__ float g_o[(long)BB*NN*HSZ];
__device__ float g_t[(long)BB*NN*HSZ];
__device__ float g_h[(long)BB*NN*DFF];
__device__ float g_s[(long)BB*HEADS*NN*NN];

// ---------------- helpers ----------------
__device__ __forceinline__ unsigned f2tf32(float x) {
    unsigned r;
    asm("cvt.rna.tf32.f32 %0, %1;" : "=r"(r) : "f"(x));
    return r;
}

__device__ __forceinline__ void mma_tf32(float* c, const unsigned* a, unsigned b0, unsigned b1) {
    asm volatile(
        "mma.sync.aligned.m16n8k8.row.col.f32.tf32.tf32.f32 "
        "{%0,%1,%2,%3}, {%4,%5,%6,%7}, {%8,%9}, {%0,%1,%2,%3};\n"
        : "+f"(c[0]), "+f"(c[1]), "+f"(c[2]), "+f"(c[3])
        : "r"(a[0]), "r"(a[1]), "r"(a[2]), "r"(a[3]), "r"(b0), "r"(b1));
}

// ---------------- gather: x = concat(ents, renc[rels]) ----------------
__global__ void __launch_bounds__(256) gather_kernel(
    const float* __restrict__ ents, const int* __restrict__ rels,
    const float* __restrict__ renc)
{
    long i = (long)blockIdx.x * 256 + threadIdx.x;          // float4 index
    const long TOT = (long)BB * NN * (HSZ / 4);
    if (i >= TOT) return;
    int c  = (int)(i & (HSZ/4 - 1));                        // 0..127
    long bn = i >> 7;
    int n  = (int)(bn & (NN - 1));
    int b  = (int)(bn >> 10);
    float4 v;
    if (n < EE) {
        v = ((const float4*)ents)[((long)b*EE + n)*(HSZ/4) + c];
    } else {
        int r = rels[b*RR + (n - EE)];
        v = ((const float4*)renc)[(long)r*(HSZ/4) + c];
    }
    ((float4*)g_x)[i] = v;
}

// ---------------- tensor-core tf32 GEMM: 128x128 block tile, K-chunk 32 ----------------
// C[z][m][n] = alpha * sum_k A[z][m][k] * B'[z][k][n]  (+bias)(prelu)(+res)
// TRB=false: B stored [K][N] row-major. TRB=true: B stored [N][K] row-major (B^T).
// 256 threads = 8 warps in 4x2 grid; warp tile 32x64; mma m16n8k8 tf32.
template<bool TRB>
__global__ void __launch_bounds__(256, 2) gemm_mma(
    const float* __restrict__ A, const float* __restrict__ B, float* __restrict__ C,
    int M, int N, int K, int lda, int ldb, int ldc,
    long sAb, long sAh, long sBb, long sBh, long sCb, long sCh,
    int H, float alpha,
    const float* __restrict__ bias,
    const float* __restrict__ prelu,
    const float* __restrict__ res)
{
    constexpr int PA = 40;    // [row][k] layout pad: frag bank = (8*gid+tig)%32, all distinct
    constexpr int PB = 136;   // [k][n] layout pad: frag bank = (8*tig+gid)%32, all distinct

    __shared__ unsigned As[128 * PA];
    __shared__ unsigned Bs[TRB ? 128 * PA : 32 * PB];

    int zb = blockIdx.z / H;
    int zh = blockIdx.z - zb * H;
    const float* Ab = A + zb * sAb + zh * sAh;
    const float* Bb = B + zb * sBb + zh * sBh;
    float*       Cb = C + zb * sCb + zh * sCh;
    const float* Rb = res ? (res + zb * sCb + zh * sCh) : nullptr;

    int bm = blockIdx.y << 7;
    int bn = blockIdx.x << 7;

    int tid  = threadIdx.x;
    int warp = tid >> 5, lane = tid & 31;
    int wm = warp >> 1, wn = warp & 1;         // 4x2 warp grid
    int gid = lane >> 2, tig = lane & 3;       // mma octet ids

    float acc[2][8][4];
    #pragma unroll
    for (int mt = 0; mt < 2; mt++)
        #pragma unroll
        for (int nt = 0; nt < 8; nt++)
            #pragma unroll
            for (int i = 0; i < 4; i++) acc[mt][nt][i] = 0.f;

    // global-load index decomposition (A tile 128x32, coalesced along K)
    const int ar0 = tid >> 3;          // row base (adds 32*l)
    const int acg = tid & 7;           // float4 column within 32-k chunk

    float4 ra[4], rb[4];
    const int nch = K >> 5;

    // ---- load chunk 0 ----
    {
        const float* pa = Ab + (long)(bm + ar0) * lda + acg * 4;
        #pragma unroll
        for (int l = 0; l < 4; l++) ra[l] = *(const float4*)(pa + (long)(32 * l) * lda);
        if (TRB) {
            const float* pb = Bb + (long)(bn + ar0) * ldb + acg * 4;
            #pragma unroll
            for (int l = 0; l < 4; l++) rb[l] = *(const float4*)(pb + (long)(32 * l) * ldb);
        } else {
            const float* pb = Bb + (long)warp * ldb + bn + lane * 4;
            #pragma unroll
            for (int l = 0; l < 4; l++) rb[l] = *(const float4*)(pb + (long)(8 * l) * ldb);
        }
    }

    for (int c = 0; c < nch; c++) {
        // ---- store staged chunk to smem (tf32-rounded) ----
        #pragma unroll
        for (int l = 0; l < 4; l++) {
            uint4 u;
            u.x = f2tf32(ra[l].x); u.y = f2tf32(ra[l].y);
            u.z = f2tf32(ra[l].z); u.w = f2tf32(ra[l].w);
            *(uint4*)&As[(ar0 + 32 * l) * PA + acg * 4] = u;
        }
        #pragma unroll
        for (int l = 0; l < 4; l++) {
            uint4 u;
            u.x = f2tf32(rb[l].x); u.y = f2tf32(rb[l].y);
            u.z = f2tf32(rb[l].z); u.w = f2tf32(rb[l].w);
            if (TRB) *(uint4*)&Bs[(ar0 + 32 * l) * PA + acg * 4] = u;
            else     *(uint4*)&Bs[(warp + 8 * l) * PB + lane * 4] = u;
        }
        __syncthreads();

        // ---- prefetch next chunk into registers ----
        if (c + 1 < nch) {
            int k0 = (c + 1) << 5;
            const float* pa = Ab + (long)(bm + ar0) * lda + k0 + acg * 4;
            #pragma unroll
            for (int l = 0; l < 4; l++) ra[l] = *(const float4*)(pa + (long)(32 * l) * lda);
            if (TRB) {
                const float* pb = Bb + (long)(bn + ar0) * ldb + k0 + acg * 4;
                #pragma unroll
                for (int l = 0; l < 4; l++) rb[l] = *(const float4*)(pb + (long)(32 * l) * ldb);
            } else {
                const float* pb = Bb + (long)(k0 + warp) * ldb + bn + lane * 4;
                #pragma unroll
                for (int l = 0; l < 4; l++) rb[l] = *(const float4*)(pb + (long)(8 * l) * ldb);
            }
        }

        // ---- compute on smem chunk ----
        #pragma unroll
        for (int ks = 0; ks < 4; ks++) {
            int kk = ks * 8 + tig;
            unsigned a[2][4];
            #pragma unroll
            for (int mt = 0; mt < 2; mt++) {
                const unsigned* ap = &As[(wm * 32 + mt * 16 + gid) * PA + kk];
                a[mt][0] = ap[0];
                a[mt][1] = ap[8 * PA];
                a[mt][2] = ap[4];
                a[mt][3] = ap[8 * PA + 4];
            }
            #pragma unroll
            for (int nt = 0; nt < 8; nt++) {
                int ncol = wn * 64 + nt * 8 + gid;
                unsigned b0, b1;
                if (TRB) {
                    const unsigned* bp = &Bs[ncol * PA + kk];
                    b0 = bp[0]; b1 = bp[4];
                } else {
                    const unsigned* bp = &Bs[kk * PB + ncol];
                    b0 = bp[0]; b1 = bp[4 * PB];
                }
                mma_tf32(acc[0][nt], a[0], b0, b1);
                mma_tf32(acc[1][nt], a[1], b0, b1);
            }
        }
        if (c + 1 < nch) __syncthreads();
    }

    // ---- epilogue ----
    #pragma unroll
    for (int mt = 0; mt < 2; mt++) {
        int r0 = bm + wm * 32 + mt * 16 + gid;
        #pragma unroll
        for (int nt = 0; nt < 8; nt++) {
            int c0 = bn + wn * 64 + nt * 8 + tig * 2;
            float v0 = acc[mt][nt][0] * alpha;
            float v1 = acc[mt][nt][1] * alpha;
            float v2 = acc[mt][nt][2] * alpha;
            float v3 = acc[mt][nt][3] * alpha;
            if (bias) {
                float b0v = bias[c0], b1v = bias[c0 + 1];
                v0 += b0v; v1 += b1v; v2 += b0v; v3 += b1v;
            }
            if (prelu) {
                float p0 = prelu[c0], p1 = prelu[c0 + 1];
                v0 = v0 > 0.f ? v0 : v0 * p0;
                v1 = v1 > 0.f ? v1 : v1 * p1;
                v2 = v2 > 0.f ? v2 : v2 * p0;
                v3 = v3 > 0.f ? v3 : v3 * p1;
            }
            if (Rb) {
                float2 q0 = *(const float2*)(Rb + (long)r0 * ldc + c0);
                float2 q1 = *(const float2*)(Rb + (long)(r0 + 8) * ldc + c0);
                v0 += q0.x; v1 += q0.y; v2 += q1.x; v3 += q1.y;
            }
            *(float2*)(Cb + (long)r0 * ldc + c0)       = make_float2(v0, v1);
            *(float2*)(Cb + (long)(r0 + 8) * ldc + c0) = make_float2(v2, v3);
        }
    }
}

// ---------------- masked softmax over S rows ----------------
__global__ void __launch_bounds__(256) softmax_mask_kernel(
    float* __restrict__ S, const int* __restrict__ adj)
{
    int n = blockIdx.x, h = blockIdx.y, b = blockIdx.z;
    float* row = S + ((long)(b*HEADS + h) * NN + n) * NN;
    const int* arow = adj + ((long)b * NN + n) * NN;
    int tid = threadIdx.x;

    float4 v = ((const float4*)row)[tid];
    int4  a = ((const int4*)arow)[tid];
    v.x = a.x ? v.x : -FLT_MAX;
    v.y = a.y ? v.y : -FLT_MAX;
    v.z = a.z ? v.z : -FLT_MAX;
    v.w = a.w ? v.w : -FLT_MAX;

    __shared__ float red[16];
    int lane = tid & 31, wid = tid >> 5;

    float mx = fmaxf(fmaxf(v.x, v.y), fmaxf(v.z, v.w));
    #pragma unroll
    for (int o = 16; o > 0; o >>= 1) mx = fmaxf(mx, __shfl_xor_sync(0xffffffffu, mx, o));
    if (lane == 0) red[wid] = mx;
    __syncthreads();
    mx = red[0];
    #pragma unroll
    for (int w = 1; w < 8; w++) mx = fmaxf(mx, red[w]);

    float e0 = __expf(v.x - mx), e1 = __expf(v.y - mx);
    float e2 = __expf(v.z - mx), e3 = __expf(v.w - mx);
    float s = e0 + e1 + e2 + e3;
    #pragma unroll
    for (int o = 16; o > 0; o >>= 1) s += __shfl_xor_sync(0xffffffffu, s, o);
    if (lane == 0) red[8 + wid] = s;
    __syncthreads();
    s = red[8];
    #pragma unroll
    for (int w = 1; w < 8; w++) s += red[8 + w];

    float inv = 1.f / s;
    float4 o4 = make_float4(e0*inv, e1*inv, e2*inv, e3*inv);
    ((float4*)row)[tid] = o4;
}

// ---------------- layer norm over rows of 512 ----------------
__global__ void __launch_bounds__(128) layernorm_kernel(
    const float* __restrict__ in, float* __restrict__ out,
    const float* __restrict__ gamma, const float* __restrict__ beta)
{
    long row = blockIdx.x;
    int tid = threadIdx.x, lane = tid & 31, wid = tid >> 5;
    float4 v = ((const float4*)(in + row * HSZ))[tid];

    __shared__ float red[8];
    float s = v.x + v.y + v.z + v.w;
    #pragma unroll
    for (int o = 16; o > 0; o >>= 1) s += __shfl_xor_sync(0xffffffffu, s, o);
    if (lane == 0) red[wid] = s;
    __syncthreads();
    float mu = (red[0] + red[1] + red[2] + red[3]) * (1.f / HSZ);

    float dx = v.x - mu, dy = v.y - mu, dz = v.z - mu, dw = v.w - mu;
    float q = dx*dx + dy*dy + dz*dz + dw*dw;
    #pragma unroll
    for (int o = 16; o > 0; o >>= 1) q += __shfl_xor_sync(0xffffffffu, q, o);
    if (lane == 0) red[4 + wid] = q;
    __syncthreads();
    float var = (red[4] + red[5] + red[6] + red[7]) * (1.f / HSZ);
    float rstd = rsqrtf(var + 1e-5f);

    float4 g = ((const float4*)gamma)[tid];
    float4 bb = ((const float4*)beta)[tid];
    float4 o4;
    o4.x = dx * rstd * g.x + bb.x;
    o4.y = dy * rstd * g.y + bb.y;
    o4.z = dz * rstd * g.z + bb.z;
    o4.w = dw * rstd * g.w + bb.w;
    ((float4*)(out + row * HSZ))[tid] = o4;
}

// ---------------- output assembly: [glob | nodes | mask] ----------------
__global__ void __launch_bounds__(256) write_out_kernel(float* __restrict__ out, long out_size)
{
    long i = (long)blockIdx.x * 256 + threadIdx.x;
    if (i >= out_size) return;
    const long G  = (long)BB * HSZ;                 // 8192
    const long ND = (long)BB * NN * HSZ;            // 8388608
    if (i < G) {
        long b = i >> 9;                            // /512
        long c = i & 511;
        out[i] = g_x[(b * NN + EE) * HSZ + c];
    } else if (i < G + ND) {
        out[i] = g_x[i - G];
    } else {
        out[i] = 1.0f;                              // node_mask = True
    }
}

// ---------------- orchestration ----------------
extern "C" void kernel_launch(void* const* d_in, const int* in_sizes, int n_in,
                              void* d_out, int out_size)
{
    const float* ents = (const float*)d_in[0];
    const int*   rels = (const int*)  d_in[1];
    const int*   adj  = (const int*)  d_in[2];
    const float* renc = (const float*)d_in[3];
    const float* Wq   = (const float*)d_in[4];
    const float* Wk   = (const float*)d_in[5];
    const float* Wv   = (const float*)d_in[6];
    const float* l1w  = (const float*)d_in[7];
    const float* l1b  = (const float*)d_in[8];
    const float* l2w  = (const float*)d_in[9];
    const float* l2b  = (const float*)d_in[10];
    const float* ln1s = (const float*)d_in[11];
    const float* ln1b = (const float*)d_in[12];
    const float* ln2s = (const float*)d_in[13];
    const float* ln2b = (const float*)d_in[14];
    const float* pa   = (const float*)d_in[15];

    float *gx, *gq, *gk, *gv, *go, *gt, *gh, *gs;
    cudaGetSymbolAddress((void**)&gx, g_x);
    cudaGetSymbolAddress((void**)&gq, g_q);
    cudaGetSymbolAddress((void**)&gk, g_k);
    cudaGetSymbolAddress((void**)&gv, g_v);
    cudaGetSymbolAddress((void**)&go, g_o);
    cudaGetSymbolAddress((void**)&gt, g_t);
    cudaGetSymbolAddress((void**)&gh, g_h);
    cudaGetSymbolAddress((void**)&gs, g_s);

    const long M = (long)BB * NN;                   // 16384
    const float inv_sqrt_hsz = 0.04419417382415922f; // 1/sqrt(512)

    // gather x
    {
        long tot = M * (HSZ/4);
        gather_kernel<<<(unsigned)((tot + 255) / 256), 256>>>(ents, rels, renc);
    }

    for (int j = 0; j < PROP; j++) {
        const float* wq = Wq + (long)j * HSZ * HSZ;
        const float* wk = Wk + (long)j * HSZ * HSZ;
        const float* wv = Wv + (long)j * HSZ * HSZ;

        // Q,K,V = x @ W*
        gemm_mma<false><<<dim3(HSZ/128, (unsigned)(M/128), 1), 256>>>(
            gx, wq, gq, (int)M, HSZ, HSZ, HSZ, HSZ, HSZ,
            0,0,0,0,0,0, 1, 1.f, nullptr, nullptr, nullptr);
        gemm_mma<false><<<dim3(HSZ/128, (unsigned)(M/128), 1), 256>>>(
            gx, wk, gk, (int)M, HSZ, HSZ, HSZ, HSZ, HSZ,
            0,0,0,0,0,0, 1, 1.f, nullptr, nullptr, nullptr);
        gemm_mma<false><<<dim3(HSZ/128, (unsigned)(M/128), 1), 256>>>(
            gx, wv, gv, (int)M, HSZ, HSZ, HSZ, HSZ, HSZ,
            0,0,0,0,0,0, 1, 1.f, nullptr, nullptr, nullptr);

        // S = (Q @ K^T) / sqrt(HSZ), batched over (b,h)
        gemm_mma<true><<<dim3(NN/128, NN/128, BB*HEADS), 256>>>(
            gq, gk, gs, NN, NN, DK, HSZ, HSZ, NN,
            (long)NN*HSZ, DK, (long)NN*HSZ, DK,
            (long)HEADS*NN*NN, (long)NN*NN,
            HEADS, inv_sqrt_hsz, nullptr, nullptr, nullptr);

        // masked softmax in-place
        softmax_mask_kernel<<<dim3(NN, HEADS, BB), 256>>>(gs, adj);

        // out = S @ V + x   (residual fused)
        gemm_mma<false><<<dim3(DK/128, NN/128, BB*HEADS), 256>>>(
            gs, gv, go, NN, DK, NN, NN, HSZ, HSZ,
            (long)HEADS*NN*NN, (long)NN*NN, (long)NN*HSZ, DK,
            (long)NN*HSZ, DK,
            HEADS, 1.f, nullptr, nullptr, gx);

        // t = LN1(out)
        layernorm_kernel<<<(unsigned)M, 128>>>(go, gt, ln1s + j*HSZ, ln1b + j*HSZ);

        // h = prelu(t @ l1_w + l1_b)
        gemm_mma<false><<<dim3(DFF/128, (unsigned)(M/128), 1), 256>>>(
            gt, l1w + (long)j*HSZ*DFF, gh, (int)M, DFF, HSZ, HSZ, DFF, DFF,
            0,0,0,0,0,0, 1, 1.f, l1b + (long)j*DFF, pa + (long)j*DFF, nullptr);

        // o = h @ l2_w + l2_b + t
        gemm_mma<false><<<dim3(HSZ/128, (unsigned)(M/128), 1), 256>>>(
            gh, l2w + (long)j*DFF*HSZ, go, (int)M, HSZ, DFF, DFF, HSZ, HSZ,
            0,0,0,0,0,0, 1, 1.f, l2b + (long)j*HSZ, nullptr, gt);

        // x = LN2(o)
        layernorm_kernel<<<(unsigned)M, 128>>>(go, gx, ln2s + j*HSZ, ln2b + j*HSZ);
    }

    // assemble output: glob (16*512) | nodes (16*1024*512) | mask (16*1024)
    {
        long os = (long)out_size;
        write_out_kernel<<<(unsigned)((os + 255) / 256), 256>>>((float*)d_out, os);
    }
}